// round 2
// baseline (speedup 1.0000x reference)
#include <cuda_runtime.h>
#include <stdint.h>

#define N_NODES 50000
#define N_EDGES 400000
#define D 256

static constexpr int TOTAL_ELEMS = N_NODES * D;           // 12,800,000
static constexpr int MASK_WORDS  = TOTAL_ELEMS / 32;      // 400,000

// ---------------- scratch (device globals: no allocations allowed) ----------
__device__ int      g_deg_out[N_NODES];
__device__ int      g_deg_in [N_NODES];
__device__ int      g_off    [N_NODES + 1];
__device__ int      g_cur    [N_NODES];
__device__ int      g_srcs   [N_EDGES];
__device__ float    g_inv_out[N_NODES];
__device__ float    g_inv_in [N_NODES];
__device__ unsigned g_mask   [MASK_WORDS];
__device__ float    g_x      [(size_t)N_NODES * D];       // projected features

// ---------------- kernels ---------------------------------------------------

__global__ void k_init()
{
    int i = blockIdx.x * blockDim.x + threadIdx.x;
    if (i < N_NODES) { g_deg_out[i] = 0; g_deg_in[i] = 0; }
}

__global__ void k_degree(const int* __restrict__ src, const int* __restrict__ dst)
{
    int e = blockIdx.x * blockDim.x + threadIdx.x;
    if (e < N_EDGES) {
        atomicAdd(&g_deg_out[src[e]], 1);
        atomicAdd(&g_deg_in [dst[e]], 1);
    }
}

// single-block exclusive scan of g_deg_in -> g_off
__global__ void k_scan()
{
    __shared__ int sdata[1024];
    __shared__ int s_carry;
    int t = threadIdx.x;
    if (t == 0) s_carry = 0;
    __syncthreads();

    for (int base = 0; base < N_NODES; base += 1024) {
        int i = base + t;
        int v = (i < N_NODES) ? g_deg_in[i] : 0;
        sdata[t] = v;
        __syncthreads();
        for (int off = 1; off < 1024; off <<= 1) {
            int x = (t >= off) ? sdata[t - off] : 0;
            __syncthreads();
            sdata[t] += x;
            __syncthreads();
        }
        int incl = sdata[t];
        if (i < N_NODES) g_off[i] = s_carry + incl - v;   // exclusive
        __syncthreads();
        if (t == 0) s_carry += sdata[1023];
        __syncthreads();
    }
    if (t == 0) g_off[N_NODES] = s_carry;
}

__global__ void k_prep()
{
    int i = blockIdx.x * blockDim.x + threadIdx.x;
    if (i < N_NODES) {
        int dout = g_deg_out[i]; if (dout < 1) dout = 1;
        int din  = g_deg_in [i]; if (din  < 1) din  = 1;
        g_inv_out[i] = rsqrtf((float)dout);
        g_inv_in [i] = rsqrtf((float)din);
        g_cur[i] = g_off[i];
    }
}

__global__ void k_fill(const int* __restrict__ src, const int* __restrict__ dst)
{
    int e = blockIdx.x * blockDim.x + threadIdx.x;
    if (e < N_EDGES) {
        int p = atomicAdd(&g_cur[dst[e]], 1);
        g_srcs[p] = src[e];
    }
}

// ---- JAX threefry2x32 (key = (0, 42)), exact replication -------------------
#define TF_ROUND(r) { x0 += x1; x1 = __funnelshift_l(x1, x1, (r)); x1 ^= x0; }

__device__ __forceinline__ void threefry_0_42(unsigned& x0, unsigned& x1)
{
    const unsigned ks0 = 0u, ks1 = 42u;
    const unsigned ks2 = 0u ^ 42u ^ 0x1BD11BDAu;
    x0 += ks0; x1 += ks1;
    TF_ROUND(13) TF_ROUND(15) TF_ROUND(26) TF_ROUND(6)
    x0 += ks1; x1 += ks2 + 1u;
    TF_ROUND(17) TF_ROUND(29) TF_ROUND(16) TF_ROUND(24)
    x0 += ks2; x1 += ks0 + 2u;
    TF_ROUND(13) TF_ROUND(15) TF_ROUND(26) TF_ROUND(6)
    x0 += ks0; x1 += ks1 + 3u;
    TF_ROUND(17) TF_ROUND(29) TF_ROUND(16) TF_ROUND(24)
    x0 += ks1; x1 += ks2 + 4u;
    TF_ROUND(13) TF_ROUND(15) TF_ROUND(26) TF_ROUND(6)
    x0 += ks2; x1 += ks0 + 5u;
}

__device__ __forceinline__ bool keep_bit(unsigned bits)
{
    float u = __uint_as_float((bits >> 9) | 0x3f800000u) - 1.0f;
    return u < 0.9f;
}

// Partitionable threefry (JAX >= 0.4.36 default):
// element e -> counter (hi=0, lo=e); 32-bit output = out_hi ^ out_lo.
// One thread per element, ballot-packed into a bitmask.
__global__ void k_mask()
{
    int e = blockIdx.x * blockDim.x + threadIdx.x;   // grid exactly covers TOTAL_ELEMS
    unsigned x0 = 0u;
    unsigned x1 = (unsigned)e;
    threefry_0_42(x0, x1);
    unsigned b = __ballot_sync(0xffffffffu, keep_bit(x0 ^ x1));
    if ((threadIdx.x & 31) == 0) g_mask[e >> 5] = b;
}

// ---- GEMM: g_x = (feat * rsqrt(deg_out)) @ W  (fp32, register blocked) -----
// BM=64, BN=64, BK=16, 256 threads, 4x4 per thread
__global__ void k_gemm(const float* __restrict__ feat, const float* __restrict__ W)
{
    __shared__ float As[16][68];   // [k][m], +4 pad
    __shared__ float Bs[16][64];   // [k][n]

    int tid  = threadIdx.x;
    int row0 = blockIdx.x * 64;
    int col0 = blockIdx.y * 64;

    int arow = tid >> 2, akq = tid & 3;
    int brow = tid >> 4, bnq = tid & 15;
    int ty   = tid >> 4, tx  = tid & 15;

    int  grow  = row0 + arow;
    bool rowok = grow < N_NODES;
    float scale = rowok ? g_inv_out[grow] : 0.0f;
    const float4* fr = (const float4*)(feat + (size_t)(rowok ? grow : 0) * D);

    float acc[4][4] = {};

    for (int k0 = 0; k0 < D; k0 += 16) {
        float4 av = fr[(k0 >> 2) + akq];
        av.x *= scale; av.y *= scale; av.z *= scale; av.w *= scale;
        int ka = akq * 4;
        As[ka + 0][arow] = av.x;
        As[ka + 1][arow] = av.y;
        As[ka + 2][arow] = av.z;
        As[ka + 3][arow] = av.w;

        const float4* bp = (const float4*)(W + (size_t)(k0 + brow) * D + col0) + bnq;
        *(float4*)&Bs[brow][bnq * 4] = *bp;

        __syncthreads();

        #pragma unroll
        for (int kk = 0; kk < 16; kk++) {
            float4 a = *(const float4*)&As[kk][ty * 4];
            float4 b = *(const float4*)&Bs[kk][tx * 4];
            acc[0][0] += a.x * b.x; acc[0][1] += a.x * b.y; acc[0][2] += a.x * b.z; acc[0][3] += a.x * b.w;
            acc[1][0] += a.y * b.x; acc[1][1] += a.y * b.y; acc[1][2] += a.y * b.z; acc[1][3] += a.y * b.w;
            acc[2][0] += a.z * b.x; acc[2][1] += a.z * b.y; acc[2][2] += a.z * b.z; acc[2][3] += a.z * b.w;
            acc[3][0] += a.w * b.x; acc[3][1] += a.w * b.y; acc[3][2] += a.w * b.z; acc[3][3] += a.w * b.w;
        }
        __syncthreads();
    }

    #pragma unroll
    for (int i = 0; i < 4; i++) {
        int r = row0 + ty * 4 + i;
        if (r < N_NODES) {
            float4 o = make_float4(acc[i][0], acc[i][1], acc[i][2], acc[i][3]);
            *(float4*)(g_x + (size_t)r * D + col0 + tx * 4) = o;
        }
    }
}

// ---- gather aggregation + epilogue (one warp per dst node) -----------------
__device__ __forceinline__ float epilogue(float acc, float sc, float bb, unsigned bit)
{
    float h = fmaf(acc, sc, bb);
    h = fmaxf(h, 0.0f);
    return bit ? h * (1.0f / 0.9f) : 0.0f;
}

__global__ void k_agg(const float* __restrict__ b, float* __restrict__ out)
{
    int warp = (blockIdx.x * blockDim.x + threadIdx.x) >> 5;
    int lane = threadIdx.x & 31;
    if (warp >= N_NODES) return;

    int beg = g_off[warp], end = g_off[warp + 1];
    float4 a0 = make_float4(0.f, 0.f, 0.f, 0.f);
    float4 a1 = make_float4(0.f, 0.f, 0.f, 0.f);

    for (int i = beg; i < end; i++) {
        int s = g_srcs[i];
        const float4* xr = (const float4*)(g_x + (size_t)s * D);
        float4 v0 = xr[lane];
        float4 v1 = xr[lane + 32];
        a0.x += v0.x; a0.y += v0.y; a0.z += v0.z; a0.w += v0.w;
        a1.x += v1.x; a1.y += v1.y; a1.z += v1.z; a1.w += v1.w;
    }

    float sc = g_inv_in[warp];
    const float4* b4 = (const float4*)b;
    float4 bv0 = b4[lane];
    float4 bv1 = b4[lane + 32];

    unsigned m0 = g_mask[warp * 8 + (lane >> 3)];
    unsigned m1 = g_mask[warp * 8 + 4 + (lane >> 3)];
    int sh = (lane & 7) * 4;

    float4 o0, o1;
    o0.x = epilogue(a0.x, sc, bv0.x, (m0 >> (sh + 0)) & 1u);
    o0.y = epilogue(a0.y, sc, bv0.y, (m0 >> (sh + 1)) & 1u);
    o0.z = epilogue(a0.z, sc, bv0.z, (m0 >> (sh + 2)) & 1u);
    o0.w = epilogue(a0.w, sc, bv0.w, (m0 >> (sh + 3)) & 1u);
    o1.x = epilogue(a1.x, sc, bv1.x, (m1 >> (sh + 0)) & 1u);
    o1.y = epilogue(a1.y, sc, bv1.y, (m1 >> (sh + 1)) & 1u);
    o1.z = epilogue(a1.z, sc, bv1.z, (m1 >> (sh + 2)) & 1u);
    o1.w = epilogue(a1.w, sc, bv1.w, (m1 >> (sh + 3)) & 1u);

    float4* out4 = (float4*)(out + (size_t)warp * D);
    out4[lane]      = o0;
    out4[lane + 32] = o1;
}

// ---------------- launch -----------------------------------------------------
extern "C" void kernel_launch(void* const* d_in, const int* in_sizes, int n_in,
                              void* d_out, int out_size)
{
    const float* feat = (const float*)d_in[0];
    const float* W    = (const float*)d_in[1];
    const float* b    = (const float*)d_in[2];
    const int*   src  = (const int*)d_in[3];
    const int*   dst  = (const int*)d_in[4];
    float* out = (float*)d_out;

    k_init  <<<(N_NODES + 255) / 256, 256>>>();
    k_degree<<<(N_EDGES + 255) / 256, 256>>>(src, dst);
    k_scan  <<<1, 1024>>>();
    k_prep  <<<(N_NODES + 255) / 256, 256>>>();
    k_fill  <<<(N_EDGES + 255) / 256, 256>>>(src, dst);
    k_mask  <<<TOTAL_ELEMS / 256, 256>>>();
    {
        dim3 grid((N_NODES + 63) / 64, D / 64);
        k_gemm<<<grid, 256>>>(feat, W);
    }
    k_agg   <<<(N_NODES * 32 + 255) / 256, 256>>>(b, out);
}

// round 11
// speedup vs baseline: 2.0586x; 2.0586x over previous
#include <cuda_runtime.h>
#include <cuda_bf16.h>
#include <stdint.h>

#define N_NODES 50000
#define N_EDGES 400000
#define D 256

static constexpr int N_PAD  = 53248;           // 13 * 4096, for int4 scan
static constexpr int M_TILES = 391;            // 391*128 = 50048 >= 50000
static constexpr int M_PAD  = M_TILES * 128;   // 50048

// ---------------- scratch (device globals: no allocations allowed) ----------
__device__ int      g_deg_out[N_PAD];
__device__ int      g_deg_in [N_PAD];
__device__ int      g_off    [N_PAD + 1];
__device__ int      g_cur    [N_NODES];
__device__ int      g_srcs   [N_EDGES];
__device__ float    g_inv_out[N_NODES];
__device__ float    g_inv_in [N_NODES];
__device__ float    g_x      [(size_t)N_NODES * D];   // projected features
// Pre-swizzled bf16 hi/lo tiles.
// A: per row m: 4 chunks x 128B (k-chunk 64). B (W^T): 4 chunks x [256 n x 128B].
__device__ uint4    g_Ah[M_PAD * 32];          // 50048 * 512B
__device__ uint4    g_Al[M_PAD * 32];
__device__ uint4    g_Bh[4 * 2048];            // 4 * 32KB
__device__ uint4    g_Bl[4 * 2048];

// ---------------- asm helpers ------------------------------------------------
__device__ __forceinline__ uint32_t smem_u32(const void* p)
{
    uint32_t a;
    asm("{ .reg .u64 t; cvta.to.shared.u64 t, %1; cvt.u32.u64 %0, t; }" : "=r"(a) : "l"(p));
    return a;
}

#define CP16(sa, ga) asm volatile("cp.async.cg.shared.global [%0], [%1], 16;" :: "r"(sa), "l"(ga))
#define CP_COMMIT()  asm volatile("cp.async.commit_group;")

#define LDM4(R, a)                                                              \
    asm volatile("ldmatrix.sync.aligned.m8n8.x4.shared.b16 {%0,%1,%2,%3}, [%4];"\
        : "=r"((R)[0]), "=r"((R)[1]), "=r"((R)[2]), "=r"((R)[3]) : "r"(a))

#define MMA_BF16(d, A, B)                                                       \
    asm volatile("mma.sync.aligned.m16n8k16.row.col.f32.bf16.bf16.f32 "         \
        "{%0,%1,%2,%3},{%4,%5,%6,%7},{%8,%9},{%0,%1,%2,%3};"                    \
        : "+f"((d)[0]), "+f"((d)[1]), "+f"((d)[2]), "+f"((d)[3])                \
        : "r"((A)[0]), "r"((A)[1]), "r"((A)[2]), "r"((A)[3]),                   \
          "r"((B)[0]), "r"((B)[1]))

// ---------------- setup kernels ----------------------------------------------
__global__ void k_init()
{
    int i = blockIdx.x * blockDim.x + threadIdx.x;
    if (i < N_PAD) { g_deg_out[i] = 0; g_deg_in[i] = 0; }
}

__global__ void k_degree(const int* __restrict__ src, const int* __restrict__ dst)
{
    int e = blockIdx.x * blockDim.x + threadIdx.x;
    if (e < N_EDGES) {
        atomicAdd(&g_deg_out[src[e]], 1);
        atomicAdd(&g_deg_in [dst[e]], 1);
    }
}

// single-block scan, 4 elems/thread, shfl-based
__global__ void k_scan()
{
    __shared__ int swarp[32];
    __shared__ int s_carry, s_total;
    int t = threadIdx.x, lane = t & 31, wid = t >> 5;
    if (t == 0) s_carry = 0;
    __syncthreads();

    for (int base = 0; base < N_PAD; base += 4096) {
        int i = base + t * 4;
        int4 v = *(const int4*)&g_deg_in[i];
        int p0 = v.x, p1 = p0 + v.y, p2 = p1 + v.z, p3 = p2 + v.w;
        int s = p3;
        #pragma unroll
        for (int o = 1; o < 32; o <<= 1) {
            int x = __shfl_up_sync(0xffffffffu, s, o);
            if (lane >= o) s += x;
        }
        if (lane == 31) swarp[wid] = s;
        __syncthreads();
        if (wid == 0) {
            int ws = swarp[lane], t2 = ws;
            #pragma unroll
            for (int o = 1; o < 32; o <<= 1) {
                int x = __shfl_up_sync(0xffffffffu, t2, o);
                if (lane >= o) t2 += x;
            }
            swarp[lane] = t2 - ws;
            if (lane == 31) s_total = t2;
        }
        __syncthreads();
        int pre = s_carry + swarp[wid] + (s - p3);   // exclusive at i
        int4 o4 = make_int4(pre, pre + p0, pre + p1, pre + p2);
        *(int4*)&g_off[i] = o4;
        __syncthreads();
        if (t == 0) s_carry += s_total;
    }
    if (t == 0) g_off[N_PAD] = s_carry;
}

__global__ void k_prep()
{
    int i = blockIdx.x * blockDim.x + threadIdx.x;
    if (i < N_NODES) {
        int dout = g_deg_out[i]; if (dout < 1) dout = 1;
        int din  = g_deg_in [i]; if (din  < 1) din  = 1;
        g_inv_out[i] = rsqrtf((float)dout);
        g_inv_in [i] = rsqrtf((float)din);
        g_cur[i] = g_off[i];
    }
}

__global__ void k_fill(const int* __restrict__ src, const int* __restrict__ dst)
{
    int e = blockIdx.x * blockDim.x + threadIdx.x;
    if (e < N_EDGES) {
        int p = atomicAdd(&g_cur[dst[e]], 1);
        g_srcs[p] = src[e];
    }
}

// W^T split+swizzle: B[n][k] = W[k][n]; chunk c = k in [64c, 64c+64).
// Byte within chunk: n*128 + ((kk*2) ^ ((n&7)<<4)).
__global__ void k_wprep(const float* __restrict__ W)
{
    int idx = blockIdx.x * blockDim.x + threadIdx.x;    // 65536 = 256*256
    int k = idx >> 8, n = idx & 255;
    float w = W[idx];
    __nv_bfloat16 h = __float2bfloat16(w);
    __nv_bfloat16 l = __float2bfloat16(w - __bfloat162float(h));
    int c = k >> 6, kk = k & 63;
    uint32_t off = (uint32_t)(c * 32768 + n * 128 + (((uint32_t)kk * 2) ^ (uint32_t)((n & 7) << 4)));
    *(__nv_bfloat16*)((char*)g_Bh + off) = h;
    *(__nv_bfloat16*)((char*)g_Bl + off) = l;
}

// A split+swizzle: row m, 4 chunks x 128B; thread handles 8 k (16B out).
__global__ void k_aprep(const float* __restrict__ feat)
{
    int t = blockIdx.x * blockDim.x + threadIdx.x;      // M_PAD*32 threads
    if (t >= M_PAD * 32) return;
    int m = t >> 5, q = t & 31;                         // k = q*8
    float v[8];
    if (m < N_NODES) {
        float sc = g_inv_out[m];
        const float4* p = (const float4*)(feat + (size_t)m * D + q * 8);
        float4 f0 = p[0], f1 = p[1];
        v[0] = f0.x * sc; v[1] = f0.y * sc; v[2] = f0.z * sc; v[3] = f0.w * sc;
        v[4] = f1.x * sc; v[5] = f1.y * sc; v[6] = f1.z * sc; v[7] = f1.w * sc;
    } else {
        #pragma unroll
        for (int j = 0; j < 8; j++) v[j] = 0.0f;
    }
    __nv_bfloat16 hb[8], lb[8];
    #pragma unroll
    for (int j = 0; j < 8; j++) {
        hb[j] = __float2bfloat16(v[j]);
        lb[j] = __float2bfloat16(v[j] - __bfloat162float(hb[j]));
    }
    int chunk = q >> 3;
    uint32_t colb = ((uint32_t)((q & 7) * 16)) ^ ((uint32_t)((m & 7) << 4));
    size_t off = (((size_t)m * 4 + chunk) * 128 + colb) >> 4;   // uint4 index
    g_Ah[off] = *(uint4*)hb;
    g_Al[off] = *(uint4*)lb;
}

// ---------------- HMMA GEMM: g_x = A @ W (bf16x3) ---------------------------
// CTA 128x128, grid (391, 2). BK=64, 2-stage cp.async. 8 warps = 4m x 2n.
// Stage layout (64KB): Ah 16K | Al 16K | Bh 16K | Bl 16K.
static constexpr int GEMM_SMEM = 2 * 65536;

__global__ void __launch_bounds__(256) k_gemm()
{
    extern __shared__ char sm[];
    uint32_t sbase = smem_u32(sm);

    const int tid = threadIdx.x, lane = tid & 31;
    const int wid = tid >> 5;
    const int warp_m = wid & 3, warp_n = wid >> 2;
    const int row0 = blockIdx.x * 128;
    const int by = blockIdx.y;

    float acc[2][8][4];
    #pragma unroll
    for (int f = 0; f < 2; f++)
        #pragma unroll
        for (int j = 0; j < 8; j++)
            #pragma unroll
            for (int q = 0; q < 4; q++) acc[f][j][q] = 0.0f;

    const char* bAh = (const char*)g_Ah;
    const char* bAl = (const char*)g_Al;
    const char* bBh = (const char*)g_Bh;
    const char* bBl = (const char*)g_Bl;

    // issue chunk c into stage s
    #define ISSUE(c, s) do {                                                    \
        uint32_t dA = sbase + (s) * 65536;                                      \
        _Pragma("unroll")                                                       \
        for (int i = 0; i < 4; i++) {                                           \
            int idx = tid + i * 256;                                            \
            int r = idx >> 3, part = idx & 7;                                   \
            size_t ga = ((size_t)(row0 + r) * 4 + (c)) * 128 + part * 16;       \
            uint32_t sa = (uint32_t)(r * 128 + part * 16);                      \
            CP16(dA + sa,          bAh + ga);                                   \
            CP16(dA + 16384 + sa,  bAl + ga);                                   \
            size_t gb = (size_t)(c) * 32768 + (size_t)by * 16384 + (size_t)idx * 16; \
            CP16(dA + 32768 + (uint32_t)idx * 16, bBh + gb);                    \
            CP16(dA + 49152 + (uint32_t)idx * 16, bBl + gb);                    \
        }                                                                       \
        CP_COMMIT();                                                            \
    } while (0)

    ISSUE(0, 0);
    ISSUE(1, 1);

    const int g  = lane >> 3;      // ldmatrix address group
    const int rw = lane & 7;
    const uint32_t swz = (uint32_t)(rw << 4);

    for (int c = 0; c < 4; c++) {
        if (c < 3) asm volatile("cp.async.wait_group 1;");
        else       asm volatile("cp.async.wait_group 0;");
        __syncthreads();

        uint32_t Ah = sbase + (c & 1) * 65536;
        uint32_t Al = Ah + 16384, Bh = Ah + 32768, Bl = Ah + 49152;

        #pragma unroll
        for (int it = 0; it < 4; it++) {
            int colb = it * 32;
            uint32_t ah[2][4], al[2][4], bh[8][2], bl[8][2];

            #pragma unroll
            for (int f = 0; f < 2; f++) {
                int row = warp_m * 32 + f * 16 + (g & 1) * 8 + rw;
                uint32_t col = (uint32_t)(colb + (g >> 1) * 16) ^ swz;
                uint32_t off = (uint32_t)(row * 128) + col;
                LDM4(ah[f], Ah + off);
                LDM4(al[f], Al + off);
            }
            #pragma unroll
            for (int p = 0; p < 4; p++) {
                int n = warp_n * 64 + p * 16 + (g >> 1) * 8 + rw;
                uint32_t col = (uint32_t)(colb + (g & 1) * 16) ^ swz;
                uint32_t off = (uint32_t)(n * 128) + col;
                uint32_t r[4];
                LDM4(r, Bh + off);
                bh[2 * p][0] = r[0]; bh[2 * p][1] = r[1];
                bh[2 * p + 1][0] = r[2]; bh[2 * p + 1][1] = r[3];
                LDM4(r, Bl + off);
                bl[2 * p][0] = r[0]; bl[2 * p][1] = r[1];
                bl[2 * p + 1][0] = r[2]; bl[2 * p + 1][1] = r[3];
            }
            #pragma unroll
            for (int f = 0; f < 2; f++)
                #pragma unroll
                for (int j = 0; j < 8; j++) {
                    MMA_BF16(acc[f][j], ah[f], bh[j]);
                    MMA_BF16(acc[f][j], ah[f], bl[j]);
                    MMA_BF16(acc[f][j], al[f], bh[j]);
                }
        }
        __syncthreads();
        if (c + 2 < 4) {
            if (c == 0) ISSUE(2, 0);
            else        ISSUE(3, 1);
        }
    }

    // epilogue: d-frag rows = groupID, +8; cols = (lane&3)*2
    #pragma unroll
    for (int f = 0; f < 2; f++) {
        int r_lo = row0 + warp_m * 32 + f * 16 + (lane >> 2);
        #pragma unroll
        for (int j = 0; j < 8; j++) {
            int col = by * 128 + warp_n * 64 + j * 8 + (lane & 3) * 2;
            if (r_lo < N_NODES) {
                float2 v = make_float2(acc[f][j][0], acc[f][j][1]);
                *(float2*)&g_x[(size_t)r_lo * D + col] = v;
            }
            if (r_lo + 8 < N_NODES) {
                float2 v = make_float2(acc[f][j][2], acc[f][j][3]);
                *(float2*)&g_x[(size_t)(r_lo + 8) * D + col] = v;
            }
        }
    }
    #undef ISSUE
}

// ---- JAX threefry2x32 (key = (0, 42)), partitionable path ------------------
#define TF_ROUND(r) { x0 += x1; x1 = __funnelshift_l(x1, x1, (r)); x1 ^= x0; }

__device__ __forceinline__ bool dropout_keep(unsigned e)
{
    const unsigned ks1 = 42u;
    const unsigned ks2 = 42u ^ 0x1BD11BDAu;
    unsigned x0 = 0u, x1 = e;
    x0 += 0u; x1 += ks1;
    TF_ROUND(13) TF_ROUND(15) TF_ROUND(26) TF_ROUND(6)
    x0 += ks1; x1 += ks2 + 1u;
    TF_ROUND(17) TF_ROUND(29) TF_ROUND(16) TF_ROUND(24)
    x0 += ks2; x1 += 0u + 2u;
    TF_ROUND(13) TF_ROUND(15) TF_ROUND(26) TF_ROUND(6)
    x0 += 0u; x1 += ks1 + 3u;
    TF_ROUND(17) TF_ROUND(29) TF_ROUND(16) TF_ROUND(24)
    x0 += ks1; x1 += ks2 + 4u;
    TF_ROUND(13) TF_ROUND(15) TF_ROUND(26) TF_ROUND(6)
    x0 += ks2; x1 += 0u + 5u;
    unsigned b = x0 ^ x1;
    float u = __uint_as_float((b >> 9) | 0x3f800000u) - 1.0f;
    return u < 0.9f;
}

// ---- gather aggregation + fused dropout epilogue (one warp per dst node) ---
// Edge loop unrolled 2x with independent accumulators to double MLP.
__device__ __forceinline__ float epi(float acc, float sc, float bb, bool keep)
{
    float h = fmaf(acc, sc, bb);
    h = fmaxf(h, 0.0f);
    return keep ? h * (1.0f / 0.9f) : 0.0f;
}

__global__ void k_agg(const float* __restrict__ b, float* __restrict__ out)
{
    int warp = (blockIdx.x * blockDim.x + threadIdx.x) >> 5;
    int lane = threadIdx.x & 31;
    if (warp >= N_NODES) return;

    int beg = g_off[warp], end = g_off[warp + 1];
    float4 a0 = make_float4(0.f, 0.f, 0.f, 0.f);
    float4 a1 = make_float4(0.f, 0.f, 0.f, 0.f);
    float4 c0 = make_float4(0.f, 0.f, 0.f, 0.f);
    float4 c1 = make_float4(0.f, 0.f, 0.f, 0.f);

    int i = beg;
    for (; i + 1 < end; i += 2) {
        int s0 = g_srcs[i];
        int s1 = g_srcs[i + 1];
        const float4* x0 = (const float4*)(g_x + (size_t)s0 * D);
        const float4* x1 = (const float4*)(g_x + (size_t)s1 * D);
        float4 u0 = x0[lane];
        float4 u1 = x0[lane + 32];
        float4 w0 = x1[lane];
        float4 w1 = x1[lane + 32];
        a0.x += u0.x; a0.y += u0.y; a0.z += u0.z; a0.w += u0.w;
        a1.x += u1.x; a1.y += u1.y; a1.z += u1.z; a1.w += u1.w;
        c0.x += w0.x; c0.y += w0.y; c0.z += w0.z; c0.w += w0.w;
        c1.x += w1.x; c1.y += w1.y; c1.z += w1.z; c1.w += w1.w;
    }
    if (i < end) {
        int s = g_srcs[i];
        const float4* xr = (const float4*)(g_x + (size_t)s * D);
        float4 v0 = xr[lane];
        float4 v1 = xr[lane + 32];
        a0.x += v0.x; a0.y += v0.y; a0.z += v0.z; a0.w += v0.w;
        a1.x += v1.x; a1.y += v1.y; a1.z += v1.z; a1.w += v1.w;
    }
    a0.x += c0.x; a0.y += c0.y; a0.z += c0.z; a0.w += c0.w;
    a1.x += c1.x; a1.y += c1.y; a1.z += c1.z; a1.w += c1.w;

    float sc = g_inv_in[warp];
    const float4* b4 = (const float4*)b;
    float4 bv0 = b4[lane];
    float4 bv1 = b4[lane + 32];

    unsigned e0 = (unsigned)warp * 256u + (unsigned)lane * 4u;
    unsigned e1 = e0 + 128u;

    float4 o0, o1;
    o0.x = epi(a0.x, sc, bv0.x, dropout_keep(e0 + 0));
    o0.y = epi(a0.y, sc, bv0.y, dropout_keep(e0 + 1));
    o0.z = epi(a0.z, sc, bv0.z, dropout_keep(e0 + 2));
    o0.w = epi(a0.w, sc, bv0.w, dropout_keep(e0 + 3));
    o1.x = epi(a1.x, sc, bv1.x, dropout_keep(e1 + 0));
    o1.y = epi(a1.y, sc, bv1.y, dropout_keep(e1 + 1));
    o1.z = epi(a1.z, sc, bv1.z, dropout_keep(e1 + 2));
    o1.w = epi(a1.w, sc, bv1.w, dropout_keep(e1 + 3));

    float4* out4 = (float4*)(out + (size_t)warp * D);
    out4[lane]      = o0;
    out4[lane + 32] = o1;
}

// ---------------- launch -----------------------------------------------------
extern "C" void kernel_launch(void* const* d_in, const int* in_sizes, int n_in,
                              void* d_out, int out_size)
{
    const float* feat = (const float*)d_in[0];
    const float* W    = (const float*)d_in[1];
    const float* b    = (const float*)d_in[2];
    const int*   src  = (const int*)d_in[3];
    const int*   dst  = (const int*)d_in[4];
    float* out = (float*)d_out;

    cudaFuncSetAttribute(k_gemm, cudaFuncAttributeMaxDynamicSharedMemorySize, GEMM_SMEM);

    k_init  <<<(N_PAD + 255) / 256, 256>>>();
    k_degree<<<(N_EDGES + 255) / 256, 256>>>(src, dst);
    k_scan  <<<1, 1024>>>();
    k_prep  <<<(N_NODES + 255) / 256, 256>>>();
    k_fill  <<<(N_EDGES + 255) / 256, 256>>>(src, dst);
    k_wprep <<<256, 256>>>(W);
    k_aprep <<<(M_PAD * 32 + 255) / 256, 256>>>(feat);
    {
        dim3 grid(M_TILES, 2);
        k_gemm<<<grid, 256, GEMM_SMEM>>>();
    }
    k_agg   <<<(N_NODES * 32 + 255) / 256, 256>>>(b, out);
}